// round 4
// baseline (speedup 1.0000x reference)
#include <cuda_runtime.h>
#include <cuda_fp16.h>
#include <stdint.h>

#define BB 2
#define LL 192
#define DD 768
#define NCC 4
#define HH 256
#define KC 260            // Wmid K (H + NC)
#define NCH 4             // GEMM K chunks of 64 -> K=256 (bs handled in epilogue)

// ---------------- device scratch ----------------
__device__ float g_hp[BB * LL * HH];
__device__ float g_ha[BB * LL * NCC * HH];
// fp16 Wmid images [n][chunk][h row 256 x k 64, 128B rows, SW128] = 32 KB each
__device__ unsigned char g_Wb[NCC * NCH * 32768];

// ---------------- helpers ----------------
__device__ __forceinline__ uint32_t smem_u32(const void* p) {
    uint32_t a;
    asm("{ .reg .u64 tmp; cvta.to.shared.u64 tmp, %1; cvt.u32.u64 %0, tmp; }"
        : "=r"(a) : "l"(p));
    return a;
}
__device__ __forceinline__ void ldsm4(uint32_t* r, uint32_t addr) {
    asm volatile("ldmatrix.sync.aligned.m8n8.x4.shared.b16 {%0,%1,%2,%3}, [%4];"
                 : "=r"(r[0]), "=r"(r[1]), "=r"(r[2]), "=r"(r[3]) : "r"(addr));
}
__device__ __forceinline__ void mma16816(float* d, const uint32_t* a, const uint32_t* b) {
    asm volatile("mma.sync.aligned.m16n8k16.row.col.f32.f16.f16.f32 "
                 "{%0,%1,%2,%3}, {%4,%5,%6,%7}, {%8,%9}, {%0,%1,%2,%3};"
                 : "+f"(d[0]), "+f"(d[1]), "+f"(d[2]), "+f"(d[3])
                 : "r"(a[0]), "r"(a[1]), "r"(a[2]), "r"(a[3]), "r"(b[0]), "r"(b[1]));
}
#define CP_ASYNC16(dst, src) \
    asm volatile("cp.async.cg.shared.global [%0], [%1], 16;" :: "r"(dst), "l"(src))
#define CP_COMMIT() asm volatile("cp.async.commit_group;" ::: "memory")
#define CP_WAIT1()  asm volatile("cp.async.wait_group 1;" ::: "memory")
#define CP_WAIT0()  asm volatile("cp.async.wait_group 0;" ::: "memory")

__device__ __forceinline__ float tanh_fast(float x) {
    float e = __expf(2.0f * x);
    return 1.0f - __fdividef(2.0f, e + 1.0f);
}
__device__ __forceinline__ uint32_t pack_h2(float v0, float v1) {
    __half2 h = __floats2half2_rn(v0, v1);
    return *reinterpret_cast<uint32_t*>(&h);
}
__device__ __forceinline__ uint32_t sw128(uint32_t byte) {
    return byte ^ ((byte >> 3) & 0x70);
}

// ---------------------------------------------------------------------------
// Merged Stage 0+1: blocks 0..31 build g_Wb; blocks 32..151 do projections.
// ---------------------------------------------------------------------------
__global__ __launch_bounds__(256) void prep_proj(
    const float* __restrict__ seq,
    const float* __restrict__ Wp, const float* __restrict__ bp,
    const float* __restrict__ Wa, const float* __restrict__ ba,
    const float* __restrict__ Wmid)
{
    __shared__ float As[16][68];
    __shared__ float Bs[16][68];
    const int bid = blockIdx.x;
    const int t = threadIdx.x;

    if (bid < 32) {
        // prep: image = bid>>1 (n*4 + chunk), half = bid&1 (rows 0..127 / 128..255)
        int image = bid >> 1, half = bid & 1;
        int nn = image >> 2, ch = image & 3;
        unsigned char* dst = g_Wb + (size_t)image * 32768;
        #pragma unroll
        for (int j = 0; j < 16; j++) {
            int idx = half * 4096 + t + j * 256;   // h(256) x cpair(32)
            int hrow = idx >> 5, cp = idx & 31;
            int c = ch * 64 + cp * 2;              // always < 256 < KC
            float v0 = Wmid[((size_t)nn * KC + c) * HH + hrow];
            float v1 = Wmid[((size_t)nn * KC + c + 1) * HH + hrow];
            *(uint32_t*)(dst + sw128((uint32_t)(hrow * 128 + cp * 4))) = pack_h2(v0, v1);
        }
        return;
    }

    // proj part
    const int pb = bid - 32;
    const int tx = t & 15, ty = t >> 4;
    const int m0 = (pb / 20) * 64;
    const int n0 = (pb % 20) * 64;

    const float* Wsrc;
    int ldb, coff;
    if (n0 < HH) { Wsrc = Wp; ldb = HH;       coff = n0; }
    else         { Wsrc = Wa; ldb = NCC * HH; coff = n0 - HH; }

    float acc[4][4];
    #pragma unroll
    for (int i = 0; i < 4; i++)
        #pragma unroll
        for (int j = 0; j < 4; j++) acc[i][j] = 0.f;

    for (int k0 = 0; k0 < DD; k0 += 16) {
        __syncthreads();
        {
            int k = t & 15, mb = t >> 4;
            #pragma unroll
            for (int e = 0; e < 4; e++) {
                int m = mb + e * 16;
                As[k][m] = seq[(size_t)(m0 + m) * DD + k0 + k];
            }
        }
        {
            int nc = t & 63, kb = t >> 6;
            #pragma unroll
            for (int e = 0; e < 4; e++) {
                int k = kb + e * 4;
                Bs[k][nc] = Wsrc[(size_t)(k0 + k) * ldb + coff + nc];
            }
        }
        __syncthreads();
        #pragma unroll
        for (int k = 0; k < 16; k++) {
            float4 a = *(const float4*)&As[k][ty * 4];
            float4 b = *(const float4*)&Bs[k][tx * 4];
            acc[0][0] += a.x*b.x; acc[0][1] += a.x*b.y; acc[0][2] += a.x*b.z; acc[0][3] += a.x*b.w;
            acc[1][0] += a.y*b.x; acc[1][1] += a.y*b.y; acc[1][2] += a.y*b.z; acc[1][3] += a.y*b.w;
            acc[2][0] += a.z*b.x; acc[2][1] += a.z*b.y; acc[2][2] += a.z*b.z; acc[2][3] += a.z*b.w;
            acc[3][0] += a.w*b.x; acc[3][1] += a.w*b.y; acc[3][2] += a.w*b.z; acc[3][3] += a.w*b.w;
        }
    }

    #pragma unroll
    for (int i = 0; i < 4; i++) {
        int m_g = m0 + ty * 4 + i;
        #pragma unroll
        for (int e = 0; e < 4; e++) {
            int n_g = n0 + tx * 4 + e;
            float v = acc[i][e];
            if (n_g < HH) g_hp[(size_t)m_g * HH + n_g] = v + bp[n_g];
            else {
                int c = n_g - HH;
                g_ha[(size_t)m_g * NCC * HH + c] = v + ba[c];
            }
        }
    }
}

// ---------------------------------------------------------------------------
// Stage 2: fused mma.sync fp16 GEMM + tanh epilogue.
// CTA = (b, n) x [8 p x 8 a] = 64 rows, N=256, K=256. 256 threads (8 warps 2x4).
// 2 CTAs/SM (smem 112 KB, regs <=128).
// ---------------------------------------------------------------------------
#define OFF_BM   0                        // 256 f32
#define OFF_WO   1024                     // 256 f32
#define OFF_W2   2048                     // 4 x 256 f32 (Wmid rows 256..259)
#define OFF_BS   6144                     // 64 x 4 f32
#define OFF_RED  7168                     // 4 x 64 f32
#define OFF_HP   8192                     // 8 x 256 half
#define OFF_HA   12288                    // 8 x 256 half
#define OFF_A    16384                    // 4 chunks x 8 KB (64 m x 128 B)
#define OFF_B    49152                    // 2 bufs x 32 KB
#define SMEM_TOTAL (OFF_B + 65536)        // 114688 B = 112 KB

__global__ __launch_bounds__(256, 2) void fused_mma(
    const float* __restrict__ base_score,   // [B,L,NC,L]
    const float* __restrict__ Wmid,         // [NC,260,256]
    const float* __restrict__ bmid,         // [NC,H]
    const float* __restrict__ Wout,         // [NC,H]
    float* __restrict__ out)                // [B,L,NC,L]
{
    extern __shared__ __align__(1024) char smem[];
    const uint32_t sb = smem_u32(smem);
    const int t = threadIdx.x;
    const int lane = t & 31, warp = t >> 5;
    const int wm = warp >> 2, wn = warp & 3;     // 2 x 4 warp grid
    const int bz = blockIdx.z;
    const int b = bz >> 2, n = bz & 3;
    const int p0 = blockIdx.y * 8;
    const int a0 = blockIdx.x * 8;

    float*  bm_s = (float*)(smem + OFF_BM);
    float*  wo_s = (float*)(smem + OFF_WO);
    float*  w2_s = (float*)(smem + OFF_W2);
    float*  bs_s = (float*)(smem + OFF_BS);
    float*  red  = (float*)(smem + OFF_RED);
    __half* hp_s = (__half*)(smem + OFF_HP);
    __half* ha_s = (__half*)(smem + OFF_HA);

    // Kick off B chunk 0 prefetch (128 B per thread).
    {
        const char* src = (const char*)g_Wb + (size_t)(n * NCH) * 32768 + t * 128;
        uint32_t dst = sb + OFF_B + t * 128;
        #pragma unroll
        for (int e = 0; e < 8; e++) CP_ASYNC16(dst + e * 16, src + e * 16);
        CP_COMMIT();
    }

    // Prologue loads
    #pragma unroll
    for (int e = 0; e < 8; e++) {
        int idx = t + e * 256;                   // 2048: 8 rows x 256
        int r = idx >> 8, c = idx & 255;
        hp_s[idx] = __float2half(g_hp[(size_t)(b * LL + p0 + r) * HH + c]);
        ha_s[idx] = __float2half(g_ha[((size_t)(b * LL + a0 + r) * NCC + n) * HH + c]);
    }
    {                                            // bs: 64 m x 4 cc
        int m = t >> 2, cc = t & 3;
        int pm = m >> 3, am = m & 7;
        bs_s[t] = base_score[((size_t)(b * LL + p0 + pm) * NCC + cc) * LL + a0 + am];
    }
    #pragma unroll
    for (int e = 0; e < 4; e++) {                // w2: Wmid rows 256..259
        int idx = t + e * 256;
        int cc = idx >> 8, h = idx & 255;
        w2_s[idx] = Wmid[((size_t)n * KC + HH + cc) * HH + h];
    }
    bm_s[t] = bmid[n * HH + t];
    wo_s[t] = Wout[n * HH + t];
    __syncthreads();

    // Build A: 4 chunks x 64 m x 32 cpairs = 8192 pairs / 256 threads = 32 each
    #pragma unroll 1
    for (int j = 0; j < 32; j++) {
        int idx = t + j * 256;
        int ch = idx >> 11, rem = idx & 2047;
        int m = rem >> 5, cp = rem & 31;
        int pm = m >> 3, am = m & 7;
        int c = ch * 64 + cp * 2;
        float2 fp = __half22float2(*(__half2*)&hp_s[pm * HH + c]);
        float2 fa = __half22float2(*(__half2*)&ha_s[am * HH + c]);
        float v0 = tanh_fast(fp.x + fa.x);
        float v1 = tanh_fast(fp.y + fa.y);
        *(uint32_t*)(smem + OFF_A + ch * 8192 + sw128((uint32_t)(m * 128 + cp * 4)))
            = pack_h2(v0, v1);
    }

    // Per-lane ldmatrix address components
    const int mA   = wm * 32 + (lane & 15);
    const int kofA = (lane >> 4) * 16;
    const int nB   = wn * 64 + (lane & 7) + 8 * (lane >> 4);
    const int kofB = ((lane >> 3) & 1) * 16;

    float acc[2][8][4];
    #pragma unroll
    for (int mt = 0; mt < 2; mt++)
        #pragma unroll
        for (int nt = 0; nt < 8; nt++)
            #pragma unroll
            for (int e = 0; e < 4; e++) acc[mt][nt][e] = 0.f;

    #pragma unroll 1
    for (int ch = 0; ch < NCH; ch++) {
        const int buf = ch & 1;
        __syncthreads();                         // readers of buf^1 done; A ready (ch=0)
        if (ch + 1 < NCH) {
            const char* src = (const char*)g_Wb + (size_t)(n * NCH + ch + 1) * 32768 + t * 128;
            uint32_t dst = sb + OFF_B + (buf ^ 1) * 32768 + t * 128;
            #pragma unroll
            for (int e = 0; e < 8; e++) CP_ASYNC16(dst + e * 16, src + e * 16);
            CP_COMMIT();
            CP_WAIT1();
        } else {
            CP_WAIT0();
        }
        __syncthreads();                         // chunk ch visible

        const uint32_t abase = sb + OFF_A + ch * 8192;
        const uint32_t bbase = sb + OFF_B + buf * 32768;

        #pragma unroll
        for (int ks = 0; ks < 4; ks++) {
            uint32_t afr[2][4];
            #pragma unroll
            for (int mt = 0; mt < 2; mt++) {
                uint32_t byte = (uint32_t)((mA + mt * 16) * 128 + ks * 32 + kofA);
                ldsm4(afr[mt], abase + sw128(byte));
            }
            #pragma unroll
            for (int ntp = 0; ntp < 4; ntp++) {
                uint32_t bfr[4];
                uint32_t byte = (uint32_t)((nB + ntp * 16) * 128 + ks * 32 + kofB);
                ldsm4(bfr, bbase + sw128(byte));
                #pragma unroll
                for (int mt = 0; mt < 2; mt++) {
                    mma16816(acc[mt][2 * ntp],     afr[mt], bfr);
                    mma16816(acc[mt][2 * ntp + 1], afr[mt], bfr + 2);
                }
            }
        }
    }

    // Epilogue: pre-tanh fold bs*W2 + bmid, then tanh * Wout, reduce over h.
    float bsr[2][2][4];                          // [mt][row-half][cc]
    #pragma unroll
    for (int mt = 0; mt < 2; mt++) {
        int r0 = wm * 32 + mt * 16 + (lane >> 2);
        #pragma unroll
        for (int cc = 0; cc < 4; cc++) {
            bsr[mt][0][cc] = bs_s[r0 * 4 + cc];
            bsr[mt][1][cc] = bs_s[(r0 + 8) * 4 + cc];
        }
    }

    float pr[2][2] = {{0.f, 0.f}, {0.f, 0.f}};
    #pragma unroll
    for (int nt = 0; nt < 8; nt++) {
        int h0 = wn * 64 + nt * 8 + (lane & 3) * 2;
        float bm0 = bm_s[h0], bm1 = bm_s[h0 + 1];
        float w0 = wo_s[h0],  w1 = wo_s[h0 + 1];
        float w2c0[4], w2c1[4];
        #pragma unroll
        for (int cc = 0; cc < 4; cc++) {
            w2c0[cc] = w2_s[cc * HH + h0];
            w2c1[cc] = w2_s[cc * HH + h0 + 1];
        }
        #pragma unroll
        for (int mt = 0; mt < 2; mt++) {
            float v0 = acc[mt][nt][0] + bm0;
            float v1 = acc[mt][nt][1] + bm1;
            float v2 = acc[mt][nt][2] + bm0;
            float v3 = acc[mt][nt][3] + bm1;
            #pragma unroll
            for (int cc = 0; cc < 4; cc++) {
                v0 += bsr[mt][0][cc] * w2c0[cc];
                v1 += bsr[mt][0][cc] * w2c1[cc];
                v2 += bsr[mt][1][cc] * w2c0[cc];
                v3 += bsr[mt][1][cc] * w2c1[cc];
            }
            pr[mt][0] += tanh_fast(v0) * w0 + tanh_fast(v1) * w1;
            pr[mt][1] += tanh_fast(v2) * w0 + tanh_fast(v3) * w1;
        }
    }
    #pragma unroll
    for (int mt = 0; mt < 2; mt++)
        #pragma unroll
        for (int rh = 0; rh < 2; rh++) {
            float v = pr[mt][rh];
            v += __shfl_xor_sync(0xffffffffu, v, 1);
            v += __shfl_xor_sync(0xffffffffu, v, 2);
            if ((lane & 3) == 0)
                red[wn * 64 + wm * 32 + mt * 16 + rh * 8 + (lane >> 2)] = v;
        }
    __syncthreads();
    if (t < 64) {
        float r = red[t] + red[64 + t] + red[128 + t] + red[192 + t];
        int pm = t >> 3, am = t & 7;
        out[((size_t)(b * LL + p0 + pm) * NCC + n) * LL + a0 + am] = r;
    }
}

// ---------------------------------------------------------------------------
extern "C" void kernel_launch(void* const* d_in, const int* in_sizes, int n_in,
                              void* d_out, int out_size)
{
    const float* seq        = (const float*)d_in[0];
    const float* base_score = (const float*)d_in[1];
    const float* Wp         = (const float*)d_in[2];
    const float* bp         = (const float*)d_in[3];
    const float* Wa         = (const float*)d_in[4];
    const float* ba         = (const float*)d_in[5];
    const float* Wmid       = (const float*)d_in[6];
    const float* bmid       = (const float*)d_in[7];
    const float* Wout       = (const float*)d_in[8];
    float* out = (float*)d_out;

    prep_proj<<<152, 256>>>(seq, Wp, bp, Wa, ba, Wmid);

    cudaFuncSetAttribute(fused_mma, cudaFuncAttributeMaxDynamicSharedMemorySize,
                         SMEM_TOTAL);
    fused_mma<<<dim3(LL / 8, LL / 8, BB * NCC), 256, SMEM_TOTAL>>>(
        base_score, Wmid, bmid, Wout, out);
}